// round 7
// baseline (speedup 1.0000x reference)
#include <cuda_runtime.h>
#include <cuda_bf16.h>
#include <cuda_fp16.h>
#include <math.h>
#include <float.h>
#include <stdint.h>

#define TT 2048
#define HIDN 4096
#define NHQ 32
#define NKVH 8
#define HDIM 128
#define QKVO 6144
#define SCALE_QK 0.08838834764831845f

// ---------------- device scratch (static; no cudaMalloc) ----------------
static __device__ int8_t        g_A8[(size_t)TT * HIDN];
static __device__ float         g_asum[TT];
static __device__ int8_t        g_Wqkv8[(size_t)QKVO * HIDN];
static __device__ int8_t        g_Wo8[(size_t)HIDN * HIDN];
static __device__ float         g_qkv[(size_t)TT * QKVO];
static __device__ float         g_qr[(size_t)NHQ * TT * HDIM];   // [h][t][d]
static __device__ float         g_kr[(size_t)NKVH * TT * HDIM];  // [kvh][t][d]
static __device__ float         g_attn[(size_t)TT * HIDN];
static __device__ int8_t        g_q28[(size_t)TT * HIDN];
static __device__ float         g_s2[TT];
static __device__ float         g_sum2[TT];
static __device__ float         g_cos[TT * 64];
static __device__ float         g_sin[TT * 64];

// ---------------- RoPE table (fp64 inner) ----------------
__global__ void k_rope_tab(const int* __restrict__ pos) {
    int t = blockIdx.x, i = threadIdx.x;               // i: 0..63
    float ef = (float)(2 * i) / 128.0f;
    float invf = (float)(1.0 / pow(10000.0, (double)ef));
    float fr = (float)pos[t] * invf;                   // fp32 mul = reference rounding
    g_cos[t * 64 + i] = (float)cos((double)fr);
    g_sin[t * 64 + i] = (float)sin((double)fr);
}

// ---------------- activation prep: int32 -> int8 + row sums ----------------
__global__ void k_prep_a(const int* __restrict__ qa) {
    int t = blockIdx.x, tid = threadIdx.x;
    const int* row = qa + (size_t)t * HIDN;
    int8_t* arow = g_A8 + (size_t)t * HIDN;
    int s = 0;
    for (int c = tid; c < HIDN; c += 256) { int v = row[c]; s += v; arow[c] = (int8_t)v; }
    __shared__ int red[256];
    red[tid] = s; __syncthreads();
    for (int k = 128; k > 0; k >>= 1) { if (tid < k) red[tid] += red[tid + k]; __syncthreads(); }
    if (tid == 0) g_asum[t] = (float)red[0];
}

// ---------------- weight convert int32 -> int8 (vectorized) ----------------
__global__ void k_conv_w(const int* __restrict__ w, int8_t* __restrict__ o, int n) {
    int i = blockIdx.x * blockDim.x + threadIdx.x;
    int stride = gridDim.x * blockDim.x;
    for (int v = i; v < n / 4; v += stride) {
        int4 x = ((const int4*)w)[v];
        uint32_t p = (uint32_t)(x.x & 0xff) | ((uint32_t)(x.y & 0xff) << 8) |
                     ((uint32_t)(x.z & 0xff) << 16) | ((uint32_t)(x.w & 0xff) << 24);
        ((uint32_t*)o)[v] = p;
    }
}

// ---------------- int8 IMMA GEMM: C = A(MxK)*B(NxK)^T, fused W4A8 epilogue ----
// Exact integer arithmetic: s32 accumulate, |acc| < 2^24 so float convert exact.
#define ST8 80
__global__ __launch_bounds__(256) void k_gemm_i8(
    const int8_t* __restrict__ A, const int8_t* __restrict__ B,
    float* __restrict__ C, int M, int N, int K,
    const float* __restrict__ rs, const float* __restrict__ rsum,
    const float* __restrict__ cs, const float* __restrict__ cz)
{
    __shared__ int8_t Ash[128 * ST8];
    __shared__ int8_t Bsh[128 * ST8];
    const int tid = threadIdx.x;
    const int warp = tid >> 5, lane = tid & 31;
    const int wm = warp >> 1, wn = warp & 1;
    const int g = lane >> 2, tq = lane & 3;
    const int bm0 = blockIdx.y * 128, bn0 = blockIdx.x * 128;
    const int v0 = tid, v1 = tid + 256;
    const int ar0 = v0 >> 2, ac0 = (v0 & 3) * 16;
    const int ar1 = v1 >> 2, ac1 = (v1 & 3) * 16;
    const int8_t* Abase = A + (size_t)bm0 * K;
    const int8_t* Bbase = B + (size_t)bn0 * K;

    int acc[2][8][4];
#pragma unroll
    for (int i = 0; i < 2; i++)
#pragma unroll
        for (int j = 0; j < 8; j++) { acc[i][j][0]=0; acc[i][j][1]=0; acc[i][j][2]=0; acc[i][j][3]=0; }

    uint4 apf0 = *(const uint4*)(Abase + (size_t)ar0 * K + ac0);
    uint4 apf1 = *(const uint4*)(Abase + (size_t)ar1 * K + ac1);
    uint4 bpf0 = *(const uint4*)(Bbase + (size_t)ar0 * K + ac0);
    uint4 bpf1 = *(const uint4*)(Bbase + (size_t)ar1 * K + ac1);
    *(uint4*)&Ash[ar0 * ST8 + ac0] = apf0;  *(uint4*)&Ash[ar1 * ST8 + ac1] = apf1;
    *(uint4*)&Bsh[ar0 * ST8 + ac0] = bpf0;  *(uint4*)&Bsh[ar1 * ST8 + ac1] = bpf1;
    __syncthreads();

    const int KT = K >> 6;   // 64-wide k tiles
    for (int kb = 0; kb < KT; kb++) {
        if (kb + 1 < KT) {
            const int8_t* Ak = Abase + (kb + 1) * 64;
            const int8_t* Bk = Bbase + (kb + 1) * 64;
            apf0 = *(const uint4*)(Ak + (size_t)ar0 * K + ac0);
            apf1 = *(const uint4*)(Ak + (size_t)ar1 * K + ac1);
            bpf0 = *(const uint4*)(Bk + (size_t)ar0 * K + ac0);
            bpf1 = *(const uint4*)(Bk + (size_t)ar1 * K + ac1);
        }
#pragma unroll
        for (int ks = 0; ks < 2; ks++) {
            uint32_t af[2][4], bf[8][2];
#pragma unroll
            for (int mi = 0; mi < 2; mi++) {
                const int8_t* p = &Ash[(wm * 32 + mi * 16 + g) * ST8 + ks * 32 + 4 * tq];
                af[mi][0] = *(const uint32_t*)p;
                af[mi][1] = *(const uint32_t*)(p + 8 * ST8);
                af[mi][2] = *(const uint32_t*)(p + 16);
                af[mi][3] = *(const uint32_t*)(p + 8 * ST8 + 16);
            }
#pragma unroll
            for (int ni = 0; ni < 8; ni++) {
                const int8_t* p = &Bsh[(wn * 64 + ni * 8 + g) * ST8 + ks * 32 + 4 * tq];
                bf[ni][0] = *(const uint32_t*)p;
                bf[ni][1] = *(const uint32_t*)(p + 16);
            }
#pragma unroll
            for (int mi = 0; mi < 2; mi++)
#pragma unroll
                for (int ni = 0; ni < 8; ni++) {
                    asm volatile(
                        "mma.sync.aligned.m16n8k32.row.col.s32.s8.s8.s32 "
                        "{%0,%1,%2,%3},{%4,%5,%6,%7},{%8,%9},{%0,%1,%2,%3};\n"
                        : "+r"(acc[mi][ni][0]), "+r"(acc[mi][ni][1]),
                          "+r"(acc[mi][ni][2]), "+r"(acc[mi][ni][3])
                        : "r"(af[mi][0]), "r"(af[mi][1]), "r"(af[mi][2]), "r"(af[mi][3]),
                          "r"(bf[ni][0]), "r"(bf[ni][1]));
                }
        }
        __syncthreads();
        if (kb + 1 < KT) {
            *(uint4*)&Ash[ar0 * ST8 + ac0] = apf0;  *(uint4*)&Ash[ar1 * ST8 + ac1] = apf1;
            *(uint4*)&Bsh[ar0 * ST8 + ac0] = bpf0;  *(uint4*)&Bsh[ar1 * ST8 + ac1] = bpf1;
            __syncthreads();
        }
    }
#pragma unroll
    for (int mi = 0; mi < 2; mi++) {
        int rA = bm0 + wm * 32 + mi * 16 + g;
        int rB = rA + 8;
        float rsA = rs[rA], rmA = rsum[rA];
        float rsB = rs[rB], rmB = rsum[rB];
#pragma unroll
        for (int ni = 0; ni < 8; ni++) {
            int col = bn0 + wn * 64 + ni * 8 + 2 * tq;
            float cs0 = cs[col], cs1 = cs[col + 1];
            float cz0 = cz[col], cz1 = cz[col + 1];
            float2 o0, o1;
            o0.x = (rsA * cs0) * ((float)acc[mi][ni][0] - cz0 * rmA);
            o0.y = (rsA * cs1) * ((float)acc[mi][ni][1] - cz1 * rmA);
            o1.x = (rsB * cs0) * ((float)acc[mi][ni][2] - cz0 * rmB);
            o1.y = (rsB * cs1) * ((float)acc[mi][ni][3] - cz1 * rmB);
            *(float2*)&C[(size_t)rA * N + col] = o0;
            *(float2*)&C[(size_t)rB * N + col] = o1;
        }
    }
}

// ---------------- RoPE apply ----------------
__global__ void k_rope_apply() {
    int t = blockIdx.x, hh = blockIdx.y, i = threadIdx.x;   // i 0..63
    float c = g_cos[t * 64 + i], s = g_sin[t * 64 + i];
    if (hh < NHQ) {
        const float* base = g_qkv + (size_t)t * QKVO + hh * HDIM;
        float x1 = base[i], x2 = base[64 + i];
        float* o = g_qr + (size_t)hh * TT * HDIM + (size_t)t * HDIM;
        o[i] = x1 * c - x2 * s;  o[64 + i] = x2 * c + x1 * s;
    } else {
        int kvh = hh - NHQ;
        const float* base = g_qkv + (size_t)t * QKVO + NHQ * HDIM + kvh * HDIM;
        float x1 = base[i], x2 = base[64 + i];
        float* o = g_kr + (size_t)kvh * TT * HDIM + (size_t)t * HDIM;
        o[i] = x1 * c - x2 * s;  o[64 + i] = x2 * c + x1 * s;
    }
}

// ======================================================================
// fp16 split-precision tensor-core flash attention (unchanged from R6).
// ======================================================================
#define FS 136
#define FLASH_SMEM2 ((128 * FS * 2 + 64 * FS * 4) * 2)

__device__ __forceinline__ uint32_t s2u(const void* p) { return (uint32_t)__cvta_generic_to_shared(p); }

__device__ __forceinline__ void ldsm4(uint32_t& r0, uint32_t& r1, uint32_t& r2, uint32_t& r3, uint32_t a) {
    asm volatile("ldmatrix.sync.aligned.m8n8.x4.shared.b16 {%0,%1,%2,%3},[%4];\n"
                 : "=r"(r0), "=r"(r1), "=r"(r2), "=r"(r3) : "r"(a));
}
__device__ __forceinline__ void ldsm4t(uint32_t& r0, uint32_t& r1, uint32_t& r2, uint32_t& r3, uint32_t a) {
    asm volatile("ldmatrix.sync.aligned.m8n8.x4.trans.shared.b16 {%0,%1,%2,%3},[%4];\n"
                 : "=r"(r0), "=r"(r1), "=r"(r2), "=r"(r3) : "r"(a));
}
__device__ __forceinline__ void mmaf16(float* c, const uint32_t* a, uint32_t b0, uint32_t b1) {
    asm volatile("mma.sync.aligned.m16n8k16.row.col.f32.f16.f16.f32 "
                 "{%0,%1,%2,%3},{%4,%5,%6,%7},{%8,%9},{%0,%1,%2,%3};\n"
                 : "+f"(c[0]), "+f"(c[1]), "+f"(c[2]), "+f"(c[3])
                 : "r"(a[0]), "r"(a[1]), "r"(a[2]), "r"(a[3]), "r"(b0), "r"(b1));
}
__device__ __forceinline__ uint32_t ph2(__half a, __half b) {
    return (uint32_t)__half_as_ushort(a) | ((uint32_t)__half_as_ushort(b) << 16);
}
__device__ __forceinline__ void split4(float4 v, uint2& hi, uint2& lo) {
    __half a = __float2half_rn(v.x), b = __float2half_rn(v.y);
    __half c = __float2half_rn(v.z), d = __float2half_rn(v.w);
    hi.x = ph2(a, b); hi.y = ph2(c, d);
    lo.x = ph2(__float2half_rn(v.x - __half2float(a)), __float2half_rn(v.y - __half2float(b)));
    lo.y = ph2(__float2half_rn(v.z - __half2float(c)), __float2half_rn(v.w - __half2float(d)));
}
__device__ __forceinline__ void splitp(float x, float y, uint32_t& hi, uint32_t& lo) {
    __half a = __float2half_rn(x), b = __float2half_rn(y);
    hi = ph2(a, b);
    lo = ph2(__float2half_rn(x - __half2float(a)), __float2half_rn(y - __half2float(b)));
}

__global__ __launch_bounds__(256) void k_flash2() {
    extern __shared__ __half hsm[];
    __half* Qh = hsm;
    __half* Ql = Qh + 128 * FS;
    __half* Kh = Ql + 128 * FS;
    __half* Kl = Kh + 64 * FS;
    __half* Vh = Kl + 64 * FS;
    __half* Vl = Vh + 64 * FS;

    const int tid = threadIdx.x;
    const int w = tid >> 5, lane = tid & 31;
    const int g = lane >> 2, tq = lane & 3;
    const int head = blockIdx.y, kvh = head >> 2;
    const int qb = (int)(gridDim.x - 1 - blockIdx.x);
    const int q0 = qb * 128;

    const float* Qg = g_qr + (size_t)head * TT * HDIM + (size_t)q0 * HDIM;
    for (int idx = tid; idx < 128 * 32; idx += 256) {
        int r = idx >> 5, c = (idx & 31) << 2;
        float4 v = *(const float4*)&Qg[(size_t)r * HDIM + c];
        uint2 hi, lo; split4(v, hi, lo);
        *(uint2*)&Qh[r * FS + c] = hi;
        *(uint2*)&Ql[r * FS + c] = lo;
    }

    const int l7 = lane & 7, sel = lane >> 3;
    uint32_t aQh = s2u(Qh) + ((16 * w + (sel & 1) * 8 + l7) * FS + (sel >> 1) * 8) * 2;
    uint32_t aQl = aQh + 128 * FS * 2;
    uint32_t aKh = s2u(Kh) + (((sel >> 1) * 8 + l7) * FS + (sel & 1) * 8) * 2;
    uint32_t aKl = aKh + 64 * FS * 2;
    uint32_t aVh = s2u(Vh) + (((sel & 1) * 8 + l7) * FS + (sel >> 1) * 8) * 2;
    uint32_t aVl = aVh + 64 * FS * 2;

    float m0r = -INFINITY, m1r = -INFINITY, l0r = 0.f, l1r = 0.f;
    float O[16][4];
#pragma unroll
    for (int t = 0; t < 16; t++) { O[t][0]=0.f; O[t][1]=0.f; O[t][2]=0.f; O[t][3]=0.f; }

    const float* Kg = g_kr + (size_t)kvh * TT * HDIM;
    const float* Vg = g_qkv + (NHQ + NKVH) * HDIM + kvh * HDIM;
    const int rowg = q0 + 16 * w + g;
    const int nkb = 2 * qb + 2;

    for (int kb = 0; kb < nkb; kb++) {
        int k0 = kb * 64;
        __syncthreads();
        for (int idx = tid; idx < 64 * 32; idx += 256) {
            int r = idx >> 5, c = (idx & 31) << 2;
            uint2 hi, lo;
            float4 kv4 = *(const float4*)&Kg[(size_t)(k0 + r) * HDIM + c];
            split4(kv4, hi, lo);
            *(uint2*)&Kh[r * FS + c] = hi;  *(uint2*)&Kl[r * FS + c] = lo;
            float4 vv4 = *(const float4*)&Vg[(size_t)(k0 + r) * QKVO + c];
            split4(vv4, hi, lo);
            *(uint2*)&Vh[r * FS + c] = hi;  *(uint2*)&Vl[r * FS + c] = lo;
        }
        __syncthreads();

        float sc[8][4];
#pragma unroll
        for (int j = 0; j < 8; j++) { sc[j][0]=0.f; sc[j][1]=0.f; sc[j][2]=0.f; sc[j][3]=0.f; }
#pragma unroll
        for (int kt = 0; kt < 8; kt++) {
            uint32_t qa[4], ql_[4], kh[4], kl_[4];
            ldsm4(qa[0], qa[1], qa[2], qa[3], aQh + 32 * kt);
            ldsm4(ql_[0], ql_[1], ql_[2], ql_[3], aQl + 32 * kt);
#pragma unroll
            for (int p = 0; p < 4; p++) {
                ldsm4(kh[0], kh[1], kh[2], kh[3], aKh + 4352 * p + 32 * kt);
                ldsm4(kl_[0], kl_[1], kl_[2], kl_[3], aKl + 4352 * p + 32 * kt);
                mmaf16(sc[2 * p],     qa,  kh[0], kh[1]);
                mmaf16(sc[2 * p],     qa,  kl_[0], kl_[1]);
                mmaf16(sc[2 * p],     ql_, kh[0], kh[1]);
                mmaf16(sc[2 * p + 1], qa,  kh[2], kh[3]);
                mmaf16(sc[2 * p + 1], qa,  kl_[2], kl_[3]);
                mmaf16(sc[2 * p + 1], ql_, kh[2], kh[3]);
            }
        }

        bool tail = (kb >= 2 * qb);
#pragma unroll
        for (int j = 0; j < 8; j++) {
            int cb = k0 + 8 * j + 2 * tq;
#pragma unroll
            for (int e = 0; e < 2; e++) {
                float v0 = sc[j][e] * SCALE_QK;
                float v1 = sc[j][2 + e] * SCALE_QK;
                if (tail) {
                    if (cb + e > rowg)     v0 = -INFINITY;
                    if (cb + e > rowg + 8) v1 = -INFINITY;
                }
                sc[j][e] = v0; sc[j][2 + e] = v1;
            }
        }

        float mx0 = -INFINITY, mx1 = -INFINITY;
#pragma unroll
        for (int j = 0; j < 8; j++) {
            mx0 = fmaxf(mx0, fmaxf(sc[j][0], sc[j][1]));
            mx1 = fmaxf(mx1, fmaxf(sc[j][2], sc[j][3]));
        }
        mx0 = fmaxf(mx0, __shfl_xor_sync(0xffffffffu, mx0, 1));
        mx0 = fmaxf(mx0, __shfl_xor_sync(0xffffffffu, mx0, 2));
        mx1 = fmaxf(mx1, __shfl_xor_sync(0xffffffffu, mx1, 1));
        mx1 = fmaxf(mx1, __shfl_xor_sync(0xffffffffu, mx1, 2));
        float mn0 = fmaxf(m0r, mx0), mn1 = fmaxf(m1r, mx1);
        float c0 = __expf(m0r - mn0), c1 = __expf(m1r - mn1);
        m0r = mn0; m1r = mn1;
        float s0 = 0.f, s1 = 0.f;
#pragma unroll
        for (int j = 0; j < 8; j++) {
            sc[j][0] = __expf(sc[j][0] - mn0) * 1024.0f;
            sc[j][1] = __expf(sc[j][1] - mn0) * 1024.0f;
            sc[j][2] = __expf(sc[j][2] - mn1) * 1024.0f;
            sc[j][3] = __expf(sc[j][3] - mn1) * 1024.0f;
            s0 += sc[j][0] + sc[j][1];
            s1 += sc[j][2] + sc[j][3];
        }
        s0 += __shfl_xor_sync(0xffffffffu, s0, 1);
        s0 += __shfl_xor_sync(0xffffffffu, s0, 2);
        s1 += __shfl_xor_sync(0xffffffffu, s1, 1);
        s1 += __shfl_xor_sync(0xffffffffu, s1, 2);
        l0r = l0r * c0 + s0;
        l1r = l1r * c1 + s1;
#pragma unroll
        for (int t = 0; t < 16; t++) { O[t][0] *= c0; O[t][1] *= c0; O[t][2] *= c1; O[t][3] *= c1; }

#pragma unroll
        for (int jj = 0; jj < 4; jj++) {
            uint32_t pa[4], pl[4];
            splitp(sc[2 * jj][0],     sc[2 * jj][1],     pa[0], pl[0]);
            splitp(sc[2 * jj][2],     sc[2 * jj][3],     pa[1], pl[1]);
            splitp(sc[2 * jj + 1][0], sc[2 * jj + 1][1], pa[2], pl[2]);
            splitp(sc[2 * jj + 1][2], sc[2 * jj + 1][3], pa[3], pl[3]);
#pragma unroll
            for (int q = 0; q < 8; q++) {
                uint32_t vh[4], vl_[4];
                ldsm4t(vh[0], vh[1], vh[2], vh[3], aVh + 4352 * jj + 32 * q);
                ldsm4t(vl_[0], vl_[1], vl_[2], vl_[3], aVl + 4352 * jj + 32 * q);
                mmaf16(O[2 * q],     pa, vh[0], vh[1]);
                mmaf16(O[2 * q],     pa, vl_[0], vl_[1]);
                mmaf16(O[2 * q],     pl, vh[0], vh[1]);
                mmaf16(O[2 * q + 1], pa, vh[2], vh[3]);
                mmaf16(O[2 * q + 1], pa, vl_[2], vl_[3]);
                mmaf16(O[2 * q + 1], pl, vh[2], vh[3]);
            }
        }
    }

#pragma unroll
    for (int t = 0; t < 16; t++) {
        int col = head * HDIM + 8 * t + 2 * tq;
        float2 u;
        u.x = O[t][0] / l0r;  u.y = O[t][1] / l0r;
        *(float2*)&g_attn[(size_t)rowg * HIDN + col] = u;
        u.x = O[t][2] / l1r;  u.y = O[t][3] / l1r;
        *(float2*)&g_attn[(size_t)(rowg + 8) * HIDN + col] = u;
    }
}

// ---------------- dynamic quant with sum -> int8 ----------------
__global__ __launch_bounds__(256) void k_quant() {
    __shared__ float xrow[HIDN];
    __shared__ float red[256];
    int t = blockIdx.x, tid = threadIdx.x;
    const float* src = g_attn + (size_t)t * HIDN;
    float amax = 0.f;
    for (int c = tid; c < HIDN; c += 256) { float x = src[c]; xrow[c] = x; amax = fmaxf(amax, fabsf(x)); }
    red[tid] = amax; __syncthreads();
    for (int k = 128; k > 0; k >>= 1) { if (tid < k) red[tid] = fmaxf(red[tid], red[tid + k]); __syncthreads(); }
    float s = fmaxf(red[0], 1e-8f) / 127.0f;
    int8_t* q = g_q28 + (size_t)t * HIDN;
    float qs = 0.f;
    for (int c = tid; c < HIDN; c += 256) {
        float v = rintf(xrow[c] / s);
        v = fminf(fmaxf(v, -127.f), 127.f);
        q[c] = (int8_t)v;
        qs += v;
    }
    __syncthreads();
    red[tid] = qs; __syncthreads();
    for (int k = 128; k > 0; k >>= 1) { if (tid < k) red[tid] += red[tid + k]; __syncthreads(); }
    if (tid == 0) { g_s2[t] = s; g_sum2[t] = red[0]; }
}

// ---------------- launch ----------------
extern "C" void kernel_launch(void* const* d_in, const int* in_sizes, int n_in,
                              void* d_out, int out_size) {
    const int*   positions   = (const int*)d_in[0];
    const int*   q_act       = (const int*)d_in[1];
    const float* act_scale   = (const float*)d_in[2];
    const int*   w_qkv_q     = (const int*)d_in[3];
    const float* w_qkv_scale = (const float*)d_in[4];
    const float* w_qkv_zero  = (const float*)d_in[5];
    const int*   w_o_q       = (const int*)d_in[6];
    const float* w_o_scale   = (const float*)d_in[7];
    const float* w_o_zero    = (const float*)d_in[8];
    float* out = (float*)d_out;

    int8_t *A8, *Wqkv8, *Wo8, *q28;
    float *asum, *qkv, *s2, *sum2;
    cudaGetSymbolAddress((void**)&A8,    g_A8);
    cudaGetSymbolAddress((void**)&Wqkv8, g_Wqkv8);
    cudaGetSymbolAddress((void**)&Wo8,   g_Wo8);
    cudaGetSymbolAddress((void**)&q28,   g_q28);
    cudaGetSymbolAddress((void**)&asum,  g_asum);
    cudaGetSymbolAddress((void**)&qkv,   g_qkv);
    cudaGetSymbolAddress((void**)&s2,    g_s2);
    cudaGetSymbolAddress((void**)&sum2,  g_sum2);

    cudaFuncSetAttribute(k_flash2, cudaFuncAttributeMaxDynamicSharedMemorySize, FLASH_SMEM2);

    k_rope_tab<<<TT, 64>>>(positions);
    k_prep_a<<<TT, 256>>>(q_act);
    k_conv_w<<<2048, 256>>>(w_qkv_q, Wqkv8, QKVO * HIDN);
    k_conv_w<<<2048, 256>>>(w_o_q, Wo8, HIDN * HIDN);

    dim3 g1(QKVO / 128, TT / 128);
    k_gemm_i8<<<g1, 256>>>(A8, Wqkv8, qkv, TT, QKVO, HIDN, act_scale, asum, w_qkv_scale, w_qkv_zero);

    dim3 g2(TT, NHQ + NKVH);
    k_rope_apply<<<g2, 64>>>();

    dim3 g3(TT / 128, NHQ);
    k_flash2<<<g3, 256, FLASH_SMEM2>>>();

    k_quant<<<TT, 256>>>();

    dim3 g4(HIDN / 128, TT / 128);
    k_gemm_i8<<<g4, 256>>>(q28, Wo8, out, TT, HIDN, HIDN, s2, sum2, w_o_scale, w_o_zero);
}

// round 8
// speedup vs baseline: 1.4874x; 1.4874x over previous
#include <cuda_runtime.h>
#include <cuda_bf16.h>
#include <cuda_fp16.h>
#include <math.h>
#include <float.h>
#include <stdint.h>

#define TT 2048
#define HIDN 4096
#define NHQ 32
#define NKVH 8
#define HDIM 128
#define QKVO 6144
#define SCALE_QK 0.08838834764831845f

// ---------------- device scratch (static; no cudaMalloc) ----------------
static __device__ __nv_bfloat16 g_A[(size_t)TT * HIDN];
static __device__ float         g_asum[TT];
static __device__ __nv_bfloat16 g_Wqkv[(size_t)QKVO * HIDN];
static __device__ __nv_bfloat16 g_Wo[(size_t)HIDN * HIDN];
static __device__ float         g_qkv[(size_t)TT * QKVO];
static __device__ float         g_qr[(size_t)NHQ * TT * HDIM];   // [h][t][d]
static __device__ float         g_kr[(size_t)NKVH * TT * HDIM];  // [kvh][t][d]
static __device__ float         g_attn[(size_t)TT * HIDN];
static __device__ __nv_bfloat16 g_q2[(size_t)TT * HIDN];
static __device__ float         g_s2[TT];
static __device__ float         g_sum2[TT];
static __device__ float         g_cos[TT * 64];
static __device__ float         g_sin[TT * 64];

__device__ __forceinline__ uint32_t s2u(const void* p) { return (uint32_t)__cvta_generic_to_shared(p); }

// ---------------- RoPE table (fp64 inner) ----------------
__global__ void k_rope_tab(const int* __restrict__ pos) {
    int t = blockIdx.x, i = threadIdx.x;               // i: 0..63
    float ef = (float)(2 * i) / 128.0f;
    float invf = (float)(1.0 / pow(10000.0, (double)ef));
    float fr = (float)pos[t] * invf;                   // fp32 mul = reference rounding
    g_cos[t * 64 + i] = (float)cos((double)fr);
    g_sin[t * 64 + i] = (float)sin((double)fr);
}

// ---------------- activation prep ----------------
__global__ void k_prep_a(const int* __restrict__ qa) {
    int t = blockIdx.x, tid = threadIdx.x;
    const int* row = qa + (size_t)t * HIDN;
    __nv_bfloat16* arow = g_A + (size_t)t * HIDN;
    int s = 0;
    for (int c = tid; c < HIDN; c += 256) { int v = row[c]; s += v; arow[c] = __float2bfloat16((float)v); }
    __shared__ int red[256];
    red[tid] = s; __syncthreads();
    for (int k = 128; k > 0; k >>= 1) { if (tid < k) red[tid] += red[tid + k]; __syncthreads(); }
    if (tid == 0) g_asum[t] = (float)red[0];
}

__global__ void k_conv_w(const int* __restrict__ w, __nv_bfloat16* __restrict__ o, int n) {
    int i = blockIdx.x * blockDim.x + threadIdx.x;
    int stride = gridDim.x * blockDim.x;
    for (int v = i; v < n / 4; v += stride) {
        int4 x = ((const int4*)w)[v];
        __nv_bfloat162 p0 = {__float2bfloat16((float)x.x), __float2bfloat16((float)x.y)};
        __nv_bfloat162 p1 = {__float2bfloat16((float)x.z), __float2bfloat16((float)x.w)};
        ((__nv_bfloat162*)o)[2 * v] = p0;
        ((__nv_bfloat162*)o)[2 * v + 1] = p1;
    }
}

// ==================================================================
// bf16 HMMA GEMM v2: C = A(MxK)*B(NxK)^T, fused W4A8 epilogue.
// 2-stage cp.async smem pipeline, ldmatrix fragment loads,
// one __syncthreads per 32-k tile. Bit-exact integer arithmetic.
// ==================================================================
#define GST 40                       // smem row stride in bf16
#define GSTAGE (128 * GST * 2)       // stage bytes = 10240

__device__ __forceinline__ void ldsm4(uint32_t& r0, uint32_t& r1, uint32_t& r2, uint32_t& r3, uint32_t a) {
    asm volatile("ldmatrix.sync.aligned.m8n8.x4.shared.b16 {%0,%1,%2,%3},[%4];\n"
                 : "=r"(r0), "=r"(r1), "=r"(r2), "=r"(r3) : "r"(a));
}
__device__ __forceinline__ void mmabf(float* c, const uint32_t* a, uint32_t b0, uint32_t b1) {
    asm volatile("mma.sync.aligned.m16n8k16.row.col.f32.bf16.bf16.f32 "
                 "{%0,%1,%2,%3},{%4,%5,%6,%7},{%8,%9},{%0,%1,%2,%3};\n"
                 : "+f"(c[0]), "+f"(c[1]), "+f"(c[2]), "+f"(c[3])
                 : "r"(a[0]), "r"(a[1]), "r"(a[2]), "r"(a[3]), "r"(b0), "r"(b1));
}
#define CP16(dst, src) asm volatile("cp.async.cg.shared.global [%0], [%1], 16;\n" :: "r"(dst), "l"(src))
#define CPCOMMIT()     asm volatile("cp.async.commit_group;\n")
#define CPWAIT0()      asm volatile("cp.async.wait_group 0;\n" ::: "memory")

__global__ __launch_bounds__(256) void k_gemm(
    const __nv_bfloat16* __restrict__ A, const __nv_bfloat16* __restrict__ B,
    float* __restrict__ C, int M, int N, int K,
    const float* __restrict__ rs, const float* __restrict__ rsum,
    const float* __restrict__ cs, const float* __restrict__ cz)
{
    __shared__ __nv_bfloat16 Ash[2 * 128 * GST];
    __shared__ __nv_bfloat16 Bsh[2 * 128 * GST];
    const int tid = threadIdx.x;
    const int warp = tid >> 5, lane = tid & 31;
    const int wm = warp >> 1, wn = warp & 1;            // 4x2 warps, warp tile 32x64
    const int g = lane >> 2, tq = lane & 3;
    const int sel = lane >> 3, l7 = lane & 7;
    const int bm0 = blockIdx.y * 128, bn0 = blockIdx.x * 128;

    const int r0 = tid >> 2, c0 = (tid & 3) * 8;        // loader: rows r0, r0+64
    const __nv_bfloat16* Abase = A + (size_t)bm0 * K + (size_t)r0 * K + c0;
    const __nv_bfloat16* Bbase = B + (size_t)bn0 * K + (size_t)r0 * K + c0;
    const size_t rowK64 = (size_t)64 * K;

    uint32_t sA = s2u(Ash), sB = s2u(Bsh);
    uint32_t dA = sA + (r0 * GST + c0) * 2;
    uint32_t dB = sB + (r0 * GST + c0) * 2;

    // ldmatrix base addresses (stage 0)
    uint32_t aA = sA + ((wm * 32 + (sel & 1) * 8 + l7) * GST + (sel >> 1) * 8) * 2;
    uint32_t aB = sB + ((wn * 64 + (sel >> 1) * 8 + l7) * GST + (sel & 1) * 8) * 2;

    float acc[2][8][4];
#pragma unroll
    for (int i = 0; i < 2; i++)
#pragma unroll
        for (int j = 0; j < 8; j++) { acc[i][j][0]=0.f; acc[i][j][1]=0.f; acc[i][j][2]=0.f; acc[i][j][3]=0.f; }

    // preload stage 0
    CP16(dA, Abase);            CP16(dA + 64 * GST * 2, Abase + rowK64);
    CP16(dB, Bbase);            CP16(dB + 64 * GST * 2, Bbase + rowK64);
    CPCOMMIT();
    CPWAIT0();
    __syncthreads();

    const int KT = K >> 5;
    for (int kb = 0; kb < KT; kb++) {
        int st = (kb & 1) * GSTAGE;
        if (kb + 1 < KT) {
            int ns = ((kb + 1) & 1) * GSTAGE;
            const __nv_bfloat16* Ak = Abase + (kb + 1) * 32;
            const __nv_bfloat16* Bk = Bbase + (kb + 1) * 32;
            CP16(dA + ns, Ak);  CP16(dA + ns + 64 * GST * 2, Ak + rowK64);
            CP16(dB + ns, Bk);  CP16(dB + ns + 64 * GST * 2, Bk + rowK64);
            CPCOMMIT();
        }
#pragma unroll
        for (int ks = 0; ks < 2; ks++) {
            uint32_t af[2][4], bf[4][4];
            ldsm4(af[0][0], af[0][1], af[0][2], af[0][3], aA + st + ks * 32);
            ldsm4(af[1][0], af[1][1], af[1][2], af[1][3], aA + st + 16 * GST * 2 + ks * 32);
#pragma unroll
            for (int p = 0; p < 4; p++)
                ldsm4(bf[p][0], bf[p][1], bf[p][2], bf[p][3], aB + st + p * 16 * GST * 2 + ks * 32);
#pragma unroll
            for (int mi = 0; mi < 2; mi++)
#pragma unroll
                for (int p = 0; p < 4; p++) {
                    mmabf(acc[mi][2 * p],     af[mi], bf[p][0], bf[p][1]);
                    mmabf(acc[mi][2 * p + 1], af[mi], bf[p][2], bf[p][3]);
                }
        }
        if (kb + 1 < KT) {
            CPWAIT0();
            __syncthreads();
        }
    }

    // epilogue: out = (s_a*s_w) * (acc - z_w*a_sum)   (reference op order)
#pragma unroll
    for (int mi = 0; mi < 2; mi++) {
        int rA = bm0 + wm * 32 + mi * 16 + g;
        int rB = rA + 8;
        float rsA = rs[rA], rmA = rsum[rA];
        float rsB = rs[rB], rmB = rsum[rB];
#pragma unroll
        for (int ni = 0; ni < 8; ni++) {
            int col = bn0 + wn * 64 + ni * 8 + 2 * tq;
            float cs0 = cs[col], cs1 = cs[col + 1];
            float cz0 = cz[col], cz1 = cz[col + 1];
            float2 o0, o1;
            o0.x = (rsA * cs0) * (acc[mi][ni][0] - cz0 * rmA);
            o0.y = (rsA * cs1) * (acc[mi][ni][1] - cz1 * rmA);
            o1.x = (rsB * cs0) * (acc[mi][ni][2] - cz0 * rmB);
            o1.y = (rsB * cs1) * (acc[mi][ni][3] - cz1 * rmB);
            *(float2*)&C[(size_t)rA * N + col] = o0;
            *(float2*)&C[(size_t)rB * N + col] = o1;
        }
    }
}

// ---------------- RoPE apply ----------------
__global__ void k_rope_apply() {
    int t = blockIdx.x, hh = blockIdx.y, i = threadIdx.x;   // i 0..63
    float c = g_cos[t * 64 + i], s = g_sin[t * 64 + i];
    if (hh < NHQ) {
        const float* base = g_qkv + (size_t)t * QKVO + hh * HDIM;
        float x1 = base[i], x2 = base[64 + i];
        float* o = g_qr + (size_t)hh * TT * HDIM + (size_t)t * HDIM;
        o[i] = x1 * c - x2 * s;  o[64 + i] = x2 * c + x1 * s;
    } else {
        int kvh = hh - NHQ;
        const float* base = g_qkv + (size_t)t * QKVO + NHQ * HDIM + kvh * HDIM;
        float x1 = base[i], x2 = base[64 + i];
        float* o = g_kr + (size_t)kvh * TT * HDIM + (size_t)t * HDIM;
        o[i] = x1 * c - x2 * s;  o[64 + i] = x2 * c + x1 * s;
    }
}

// ======================================================================
// fp16 split-precision tensor-core flash attention (unchanged from R6).
// ======================================================================
#define FS 136
#define FLASH_SMEM2 ((128 * FS * 2 + 64 * FS * 4) * 2)

__device__ __forceinline__ void ldsm4t(uint32_t& r0, uint32_t& r1, uint32_t& r2, uint32_t& r3, uint32_t a) {
    asm volatile("ldmatrix.sync.aligned.m8n8.x4.trans.shared.b16 {%0,%1,%2,%3},[%4];\n"
                 : "=r"(r0), "=r"(r1), "=r"(r2), "=r"(r3) : "r"(a));
}
__device__ __forceinline__ void mmaf16(float* c, const uint32_t* a, uint32_t b0, uint32_t b1) {
    asm volatile("mma.sync.aligned.m16n8k16.row.col.f32.f16.f16.f32 "
                 "{%0,%1,%2,%3},{%4,%5,%6,%7},{%8,%9},{%0,%1,%2,%3};\n"
                 : "+f"(c[0]), "+f"(c[1]), "+f"(c[2]), "+f"(c[3])
                 : "r"(a[0]), "r"(a[1]), "r"(a[2]), "r"(a[3]), "r"(b0), "r"(b1));
}
__device__ __forceinline__ uint32_t ph2(__half a, __half b) {
    return (uint32_t)__half_as_ushort(a) | ((uint32_t)__half_as_ushort(b) << 16);
}
__device__ __forceinline__ void split4(float4 v, uint2& hi, uint2& lo) {
    __half a = __float2half_rn(v.x), b = __float2half_rn(v.y);
    __half c = __float2half_rn(v.z), d = __float2half_rn(v.w);
    hi.x = ph2(a, b); hi.y = ph2(c, d);
    lo.x = ph2(__float2half_rn(v.x - __half2float(a)), __float2half_rn(v.y - __half2float(b)));
    lo.y = ph2(__float2half_rn(v.z - __half2float(c)), __float2half_rn(v.w - __half2float(d)));
}
__device__ __forceinline__ void splitp(float x, float y, uint32_t& hi, uint32_t& lo) {
    __half a = __float2half_rn(x), b = __float2half_rn(y);
    hi = ph2(a, b);
    lo = ph2(__float2half_rn(x - __half2float(a)), __float2half_rn(y - __half2float(b)));
}

__global__ __launch_bounds__(256) void k_flash2() {
    extern __shared__ __half hsm[];
    __half* Qh = hsm;
    __half* Ql = Qh + 128 * FS;
    __half* Kh = Ql + 128 * FS;
    __half* Kl = Kh + 64 * FS;
    __half* Vh = Kl + 64 * FS;
    __half* Vl = Vh + 64 * FS;

    const int tid = threadIdx.x;
    const int w = tid >> 5, lane = tid & 31;
    const int g = lane >> 2, tq = lane & 3;
    const int head = blockIdx.y, kvh = head >> 2;
    const int qb = (int)(gridDim.x - 1 - blockIdx.x);
    const int q0 = qb * 128;

    const float* Qg = g_qr + (size_t)head * TT * HDIM + (size_t)q0 * HDIM;
    for (int idx = tid; idx < 128 * 32; idx += 256) {
        int r = idx >> 5, c = (idx & 31) << 2;
        float4 v = *(const float4*)&Qg[(size_t)r * HDIM + c];
        uint2 hi, lo; split4(v, hi, lo);
        *(uint2*)&Qh[r * FS + c] = hi;
        *(uint2*)&Ql[r * FS + c] = lo;
    }

    const int l7 = lane & 7, sel = lane >> 3;
    uint32_t aQh = s2u(Qh) + ((16 * w + (sel & 1) * 8 + l7) * FS + (sel >> 1) * 8) * 2;
    uint32_t aQl = aQh + 128 * FS * 2;
    uint32_t aKh = s2u(Kh) + (((sel >> 1) * 8 + l7) * FS + (sel & 1) * 8) * 2;
    uint32_t aKl = aKh + 64 * FS * 2;
    uint32_t aVh = s2u(Vh) + (((sel & 1) * 8 + l7) * FS + (sel >> 1) * 8) * 2;
    uint32_t aVl = aVh + 64 * FS * 2;

    float m0r = -INFINITY, m1r = -INFINITY, l0r = 0.f, l1r = 0.f;
    float O[16][4];
#pragma unroll
    for (int t = 0; t < 16; t++) { O[t][0]=0.f; O[t][1]=0.f; O[t][2]=0.f; O[t][3]=0.f; }

    const float* Kg = g_kr + (size_t)kvh * TT * HDIM;
    const float* Vg = g_qkv + (NHQ + NKVH) * HDIM + kvh * HDIM;
    const int rowg = q0 + 16 * w + g;
    const int nkb = 2 * qb + 2;

    for (int kb = 0; kb < nkb; kb++) {
        int k0 = kb * 64;
        __syncthreads();
        for (int idx = tid; idx < 64 * 32; idx += 256) {
            int r = idx >> 5, c = (idx & 31) << 2;
            uint2 hi, lo;
            float4 kv4 = *(const float4*)&Kg[(size_t)(k0 + r) * HDIM + c];
            split4(kv4, hi, lo);
            *(uint2*)&Kh[r * FS + c] = hi;  *(uint2*)&Kl[r * FS + c] = lo;
            float4 vv4 = *(const float4*)&Vg[(size_t)(k0 + r) * QKVO + c];
            split4(vv4, hi, lo);
            *(uint2*)&Vh[r * FS + c] = hi;  *(uint2*)&Vl[r * FS + c] = lo;
        }
        __syncthreads();

        float sc[8][4];
#pragma unroll
        for (int j = 0; j < 8; j++) { sc[j][0]=0.f; sc[j][1]=0.f; sc[j][2]=0.f; sc[j][3]=0.f; }
#pragma unroll
        for (int kt = 0; kt < 8; kt++) {
            uint32_t qa[4], ql_[4], kh[4], kl_[4];
            ldsm4(qa[0], qa[1], qa[2], qa[3], aQh + 32 * kt);
            ldsm4(ql_[0], ql_[1], ql_[2], ql_[3], aQl + 32 * kt);
#pragma unroll
            for (int p = 0; p < 4; p++) {
                ldsm4(kh[0], kh[1], kh[2], kh[3], aKh + 4352 * p + 32 * kt);
                ldsm4(kl_[0], kl_[1], kl_[2], kl_[3], aKl + 4352 * p + 32 * kt);
                mmaf16(sc[2 * p],     qa,  kh[0], kh[1]);
                mmaf16(sc[2 * p],     qa,  kl_[0], kl_[1]);
                mmaf16(sc[2 * p],     ql_, kh[0], kh[1]);
                mmaf16(sc[2 * p + 1], qa,  kh[2], kh[3]);
                mmaf16(sc[2 * p + 1], qa,  kl_[2], kl_[3]);
                mmaf16(sc[2 * p + 1], ql_, kh[2], kh[3]);
            }
        }

        bool tail = (kb >= 2 * qb);
#pragma unroll
        for (int j = 0; j < 8; j++) {
            int cb = k0 + 8 * j + 2 * tq;
#pragma unroll
            for (int e = 0; e < 2; e++) {
                float v0 = sc[j][e] * SCALE_QK;
                float v1 = sc[j][2 + e] * SCALE_QK;
                if (tail) {
                    if (cb + e > rowg)     v0 = -INFINITY;
                    if (cb + e > rowg + 8) v1 = -INFINITY;
                }
                sc[j][e] = v0; sc[j][2 + e] = v1;
            }
        }

        float mx0 = -INFINITY, mx1 = -INFINITY;
#pragma unroll
        for (int j = 0; j < 8; j++) {
            mx0 = fmaxf(mx0, fmaxf(sc[j][0], sc[j][1]));
            mx1 = fmaxf(mx1, fmaxf(sc[j][2], sc[j][3]));
        }
        mx0 = fmaxf(mx0, __shfl_xor_sync(0xffffffffu, mx0, 1));
        mx0 = fmaxf(mx0, __shfl_xor_sync(0xffffffffu, mx0, 2));
        mx1 = fmaxf(mx1, __shfl_xor_sync(0xffffffffu, mx1, 1));
        mx1 = fmaxf(mx1, __shfl_xor_sync(0xffffffffu, mx1, 2));
        float mn0 = fmaxf(m0r, mx0), mn1 = fmaxf(m1r, mx1);
        float c0 = __expf(m0r - mn0), c1 = __expf(m1r - mn1);
        m0r = mn0; m1r = mn1;
        float s0 = 0.f, s1 = 0.f;
#pragma unroll
        for (int j = 0; j < 8; j++) {
            sc[j][0] = __expf(sc[j][0] - mn0) * 1024.0f;
            sc[j][1] = __expf(sc[j][1] - mn0) * 1024.0f;
            sc[j][2] = __expf(sc[j][2] - mn1) * 1024.0f;
            sc[j][3] = __expf(sc[j][3] - mn1) * 1024.0f;
            s0 += sc[j][0] + sc[j][1];
            s1 += sc[j][2] + sc[j][3];
        }
        s0 += __shfl_xor_sync(0xffffffffu, s0, 1);
        s0 += __shfl_xor_sync(0xffffffffu, s0, 2);
        s1 += __shfl_xor_sync(0xffffffffu, s1, 1);
        s1 += __shfl_xor_sync(0xffffffffu, s1, 2);
        l0r = l0r * c0 + s0;
        l1r = l1r * c1 + s1;
#pragma unroll
        for (int t = 0; t < 16; t++) { O[t][0] *= c0; O[t][1] *= c0; O[t][2] *= c1; O[t][3] *= c1; }

#pragma unroll
        for (int jj = 0; jj < 4; jj++) {
            uint32_t pa[4], pl[4];
            splitp(sc[2 * jj][0],     sc[2 * jj][1],     pa[0], pl[0]);
            splitp(sc[2 * jj][2],     sc[2 * jj][3],     pa[1], pl[1]);
            splitp(sc[2 * jj + 1][0], sc[2 * jj + 1][1], pa[2], pl[2]);
            splitp(sc[2 * jj + 1][2], sc[2 * jj + 1][3], pa[3], pl[3]);
#pragma unroll
            for (int q = 0; q < 8; q++) {
                uint32_t vh[4], vl_[4];
                ldsm4t(vh[0], vh[1], vh[2], vh[3], aVh + 4352 * jj + 32 * q);
                ldsm4t(vl_[0], vl_[1], vl_[2], vl_[3], aVl + 4352 * jj + 32 * q);
                mmaf16(O[2 * q],     pa, vh[0], vh[1]);
                mmaf16(O[2 * q],     pa, vl_[0], vl_[1]);
                mmaf16(O[2 * q],     pl, vh[0], vh[1]);
                mmaf16(O[2 * q + 1], pa, vh[2], vh[3]);
                mmaf16(O[2 * q + 1], pa, vl_[2], vl_[3]);
                mmaf16(O[2 * q + 1], pl, vh[2], vh[3]);
            }
        }
    }

#pragma unroll
    for (int t = 0; t < 16; t++) {
        int col = head * HDIM + 8 * t + 2 * tq;
        float2 u;
        u.x = O[t][0] / l0r;  u.y = O[t][1] / l0r;
        *(float2*)&g_attn[(size_t)rowg * HIDN + col] = u;
        u.x = O[t][2] / l1r;  u.y = O[t][3] / l1r;
        *(float2*)&g_attn[(size_t)(rowg + 8) * HIDN + col] = u;
    }
}

// ---------------- dynamic quant with sum ----------------
__global__ __launch_bounds__(256) void k_quant() {
    __shared__ float xrow[HIDN];
    __shared__ float red[256];
    int t = blockIdx.x, tid = threadIdx.x;
    const float* src = g_attn + (size_t)t * HIDN;
    float amax = 0.f;
    for (int c = tid; c < HIDN; c += 256) { float x = src[c]; xrow[c] = x; amax = fmaxf(amax, fabsf(x)); }
    red[tid] = amax; __syncthreads();
    for (int k = 128; k > 0; k >>= 1) { if (tid < k) red[tid] = fmaxf(red[tid], red[tid + k]); __syncthreads(); }
    float s = fmaxf(red[0], 1e-8f) / 127.0f;
    __nv_bfloat16* q = g_q2 + (size_t)t * HIDN;
    float qs = 0.f;
    for (int c = tid; c < HIDN; c += 256) {
        float v = rintf(xrow[c] / s);
        v = fminf(fmaxf(v, -127.f), 127.f);
        q[c] = __float2bfloat16(v);
        qs += v;
    }
    __syncthreads();
    red[tid] = qs; __syncthreads();
    for (int k = 128; k > 0; k >>= 1) { if (tid < k) red[tid] += red[tid + k]; __syncthreads(); }
    if (tid == 0) { g_s2[t] = s; g_sum2[t] = red[0]; }
}

// ---------------- launch ----------------
extern "C" void kernel_launch(void* const* d_in, const int* in_sizes, int n_in,
                              void* d_out, int out_size) {
    const int*   positions   = (const int*)d_in[0];
    const int*   q_act       = (const int*)d_in[1];
    const float* act_scale   = (const float*)d_in[2];
    const int*   w_qkv_q     = (const int*)d_in[3];
    const float* w_qkv_scale = (const float*)d_in[4];
    const float* w_qkv_zero  = (const float*)d_in[5];
    const int*   w_o_q       = (const int*)d_in[6];
    const float* w_o_scale   = (const float*)d_in[7];
    const float* w_o_zero    = (const float*)d_in[8];
    float* out = (float*)d_out;

    __nv_bfloat16 *A, *Wqkv, *Wo, *q2;
    float *asum, *qkv, *s2, *sum2;
    cudaGetSymbolAddress((void**)&A,    g_A);
    cudaGetSymbolAddress((void**)&Wqkv, g_Wqkv);
    cudaGetSymbolAddress((void**)&Wo,   g_Wo);
    cudaGetSymbolAddress((void**)&q2,   g_q2);
    cudaGetSymbolAddress((void**)&asum, g_asum);
    cudaGetSymbolAddress((void**)&qkv,  g_qkv);
    cudaGetSymbolAddress((void**)&s2,   g_s2);
    cudaGetSymbolAddress((void**)&sum2, g_sum2);

    cudaFuncSetAttribute(k_flash2, cudaFuncAttributeMaxDynamicSharedMemorySize, FLASH_SMEM2);

    k_rope_tab<<<TT, 64>>>(positions);
    k_prep_a<<<TT, 256>>>(q_act);
    k_conv_w<<<2048, 256>>>(w_qkv_q, Wqkv, QKVO * HIDN);
    k_conv_w<<<2048, 256>>>(w_o_q, Wo, HIDN * HIDN);

    dim3 g1(QKVO / 128, TT / 128);
    k_gemm<<<g1, 256>>>(A, Wqkv, qkv, TT, QKVO, HIDN, act_scale, asum, w_qkv_scale, w_qkv_zero);

    dim3 g2(TT, NHQ + NKVH);
    k_rope_apply<<<g2, 64>>>();

    dim3 g3(TT / 128, NHQ);
    k_flash2<<<g3, 256, FLASH_SMEM2>>>();

    k_quant<<<TT, 256>>>();

    dim3 g4(HIDN / 128, TT / 128);
    k_gemm<<<g4, 256>>>(q2, Wo, out, TT, HIDN, HIDN, s2, sum2, w_o_scale, w_o_zero);
}

// round 9
// speedup vs baseline: 1.5217x; 1.0231x over previous
#include <cuda_runtime.h>
#include <cuda_bf16.h>
#include <cuda_fp16.h>
#include <math.h>
#include <float.h>
#include <stdint.h>

#define TT 2048
#define HIDN 4096
#define NHQ 32
#define NKVH 8
#define HDIM 128
#define QKVO 6144
#define SCALE_QK 0.08838834764831845f

// ---------------- device scratch (static; no cudaMalloc) ----------------
static __device__ __nv_bfloat16 g_A[(size_t)TT * HIDN];
static __device__ float         g_asum[TT];
static __device__ __nv_bfloat16 g_Wqkv[(size_t)QKVO * HIDN];
static __device__ __nv_bfloat16 g_Wo[(size_t)HIDN * HIDN];
static __device__ float         g_qkv[(size_t)TT * QKVO];
static __device__ float         g_qr[(size_t)NHQ * TT * HDIM];   // [h][t][d]
static __device__ float         g_kr[(size_t)NKVH * TT * HDIM];  // [kvh][t][d]
static __device__ float         g_attn[(size_t)TT * HIDN];
static __device__ __nv_bfloat16 g_q2[(size_t)TT * HIDN];
static __device__ float         g_s2[TT];
static __device__ float         g_sum2[TT];
static __device__ float         g_cos[TT * 64];
static __device__ float         g_sin[TT * 64];

__device__ __forceinline__ uint32_t s2u(const void* p) { return (uint32_t)__cvta_generic_to_shared(p); }

// ---------------- RoPE table (fp64 inner) ----------------
__global__ void k_rope_tab(const int* __restrict__ pos) {
    int t = blockIdx.x, i = threadIdx.x;               // i: 0..63
    float ef = (float)(2 * i) / 128.0f;
    float invf = (float)(1.0 / pow(10000.0, (double)ef));
    float fr = (float)pos[t] * invf;                   // fp32 mul = reference rounding
    g_cos[t * 64 + i] = (float)cos((double)fr);
    g_sin[t * 64 + i] = (float)sin((double)fr);
}

// ---------------- activation prep ----------------
__global__ void k_prep_a(const int* __restrict__ qa) {
    int t = blockIdx.x, tid = threadIdx.x;
    const int* row = qa + (size_t)t * HIDN;
    __nv_bfloat16* arow = g_A + (size_t)t * HIDN;
    int s = 0;
    for (int c = tid; c < HIDN; c += 256) { int v = row[c]; s += v; arow[c] = __float2bfloat16((float)v); }
    __shared__ int red[256];
    red[tid] = s; __syncthreads();
    for (int k = 128; k > 0; k >>= 1) { if (tid < k) red[tid] += red[tid + k]; __syncthreads(); }
    if (tid == 0) g_asum[t] = (float)red[0];
}

__global__ void k_conv_w(const int* __restrict__ w, __nv_bfloat16* __restrict__ o, int n) {
    int i = blockIdx.x * blockDim.x + threadIdx.x;
    int stride = gridDim.x * blockDim.x;
    for (int v = i; v < n / 4; v += stride) {
        int4 x = ((const int4*)w)[v];
        __nv_bfloat162 p0 = {__float2bfloat16((float)x.x), __float2bfloat16((float)x.y)};
        __nv_bfloat162 p1 = {__float2bfloat16((float)x.z), __float2bfloat16((float)x.w)};
        ((__nv_bfloat162*)o)[2 * v] = p0;
        ((__nv_bfloat162*)o)[2 * v + 1] = p1;
    }
}

// ==================================================================
// bf16 HMMA GEMM v3: CTA tile 256x128, warp tile 64x64 (4x2 warps),
// 3-stage cp.async pipeline, ldmatrix fragments, fused W4A8 epilogue.
// Bit-exact integer arithmetic (same k-order accumulation).
// ==================================================================
#define GST 40                         // smem row stride in bf16
#define ASTG (256 * GST)               // A stage elements
#define BSTG (128 * GST)               // B stage elements
#define GEMM_SMEM (3 * (ASTG + BSTG) * 2)   // 92160 B

__device__ __forceinline__ void ldsm4(uint32_t& r0, uint32_t& r1, uint32_t& r2, uint32_t& r3, uint32_t a) {
    asm volatile("ldmatrix.sync.aligned.m8n8.x4.shared.b16 {%0,%1,%2,%3},[%4];\n"
                 : "=r"(r0), "=r"(r1), "=r"(r2), "=r"(r3) : "r"(a));
}
__device__ __forceinline__ void mmabf(float* c, const uint32_t* a, uint32_t b0, uint32_t b1) {
    asm volatile("mma.sync.aligned.m16n8k16.row.col.f32.bf16.bf16.f32 "
                 "{%0,%1,%2,%3},{%4,%5,%6,%7},{%8,%9},{%0,%1,%2,%3};\n"
                 : "+f"(c[0]), "+f"(c[1]), "+f"(c[2]), "+f"(c[3])
                 : "r"(a[0]), "r"(a[1]), "r"(a[2]), "r"(a[3]), "r"(b0), "r"(b1));
}
#define CP16(dst, src) asm volatile("cp.async.cg.shared.global [%0], [%1], 16;\n" :: "r"(dst), "l"(src))
#define CPCOMMIT()     asm volatile("cp.async.commit_group;\n")
#define CPWAIT1()      asm volatile("cp.async.wait_group 1;\n" ::: "memory")

__global__ __launch_bounds__(256, 1) void k_gemm(
    const __nv_bfloat16* __restrict__ A, const __nv_bfloat16* __restrict__ B,
    float* __restrict__ C, int M, int N, int K,
    const float* __restrict__ rs, const float* __restrict__ rsum,
    const float* __restrict__ cs, const float* __restrict__ cz)
{
    extern __shared__ __nv_bfloat16 gsm[];
    __nv_bfloat16* Ash = gsm;
    __nv_bfloat16* Bsh = gsm + 3 * ASTG;

    const int tid = threadIdx.x;
    const int warp = tid >> 5, lane = tid & 31;
    const int wm = warp >> 1, wn = warp & 1;            // 4x2 warps, warp tile 64x64
    const int g = lane >> 2, tq = lane & 3;
    const int sel = lane >> 3, l7 = lane & 7;
    const int bm0 = blockIdx.y * 256, bn0 = blockIdx.x * 128;

    const int r0 = tid >> 2, c0 = (tid & 3) * 8;        // loader lanes
    const __nv_bfloat16* Abase = A + (size_t)(bm0 + r0) * K + c0;
    const __nv_bfloat16* Bbase = B + (size_t)(bn0 + r0) * K + c0;
    const size_t rowK64 = (size_t)64 * K;

    uint32_t sA = s2u(Ash), sB = s2u(Bsh);
    uint32_t dA = sA + (r0 * GST + c0) * 2;
    uint32_t dB = sB + (r0 * GST + c0) * 2;

    // ldmatrix base addresses within a stage
    uint32_t aA = sA + ((wm * 64 + (sel & 1) * 8 + l7) * GST + (sel >> 1) * 8) * 2;
    uint32_t aB = sB + ((wn * 64 + (sel >> 1) * 8 + l7) * GST + (sel & 1) * 8) * 2;

    float acc[4][8][4];
#pragma unroll
    for (int i = 0; i < 4; i++)
#pragma unroll
        for (int j = 0; j < 8; j++) { acc[i][j][0]=0.f; acc[i][j][1]=0.f; acc[i][j][2]=0.f; acc[i][j][3]=0.f; }

    const int KT = K >> 5;

    // preload stages 0 and 1
#pragma unroll
    for (int s = 0; s < 2; s++) {
        const __nv_bfloat16* Ak = Abase + s * 32;
        const __nv_bfloat16* Bk = Bbase + s * 32;
        uint32_t oA = dA + s * ASTG * 2, oB = dB + s * BSTG * 2;
#pragma unroll
        for (int q = 0; q < 4; q++) CP16(oA + q * 64 * GST * 2, Ak + q * rowK64);
#pragma unroll
        for (int q = 0; q < 2; q++) CP16(oB + q * 64 * GST * 2, Bk + q * rowK64);
        CPCOMMIT();
    }
    CPWAIT1();           // stage 0 resident
    __syncthreads();

    for (int kb = 0; kb < KT; kb++) {
        const int st = kb % 3;
        if (kb + 2 < KT) {
            const int ns = (kb + 2) % 3;
            const __nv_bfloat16* Ak = Abase + (kb + 2) * 32;
            const __nv_bfloat16* Bk = Bbase + (kb + 2) * 32;
            uint32_t oA = dA + ns * ASTG * 2, oB = dB + ns * BSTG * 2;
#pragma unroll
            for (int q = 0; q < 4; q++) CP16(oA + q * 64 * GST * 2, Ak + q * rowK64);
#pragma unroll
            for (int q = 0; q < 2; q++) CP16(oB + q * 64 * GST * 2, Bk + q * rowK64);
            CPCOMMIT();
        }
        const uint32_t stA = aA + st * ASTG * 2;
        const uint32_t stB = aB + st * BSTG * 2;
#pragma unroll
        for (int ks = 0; ks < 2; ks++) {
            uint32_t af[4][4], bf[4][4];
#pragma unroll
            for (int mi = 0; mi < 4; mi++)
                ldsm4(af[mi][0], af[mi][1], af[mi][2], af[mi][3], stA + mi * 16 * GST * 2 + ks * 32);
#pragma unroll
            for (int p = 0; p < 4; p++)
                ldsm4(bf[p][0], bf[p][1], bf[p][2], bf[p][3], stB + p * 16 * GST * 2 + ks * 32);
#pragma unroll
            for (int mi = 0; mi < 4; mi++)
#pragma unroll
                for (int p = 0; p < 4; p++) {
                    mmabf(acc[mi][2 * p],     af[mi], bf[p][0], bf[p][1]);
                    mmabf(acc[mi][2 * p + 1], af[mi], bf[p][2], bf[p][3]);
                }
        }
        if (kb + 1 < KT) {
            CPWAIT1();           // next stage resident (≤1 group outstanding)
            __syncthreads();
        }
    }

    // epilogue: out = (s_a*s_w) * (acc - z_w*a_sum)   (reference op order)
#pragma unroll
    for (int mi = 0; mi < 4; mi++) {
        int rA = bm0 + wm * 64 + mi * 16 + g;
        int rB = rA + 8;
        float rsA = rs[rA], rmA = rsum[rA];
        float rsB = rs[rB], rmB = rsum[rB];
#pragma unroll
        for (int ni = 0; ni < 8; ni++) {
            int col = bn0 + wn * 64 + ni * 8 + 2 * tq;
            float cs0 = cs[col], cs1 = cs[col + 1];
            float cz0 = cz[col], cz1 = cz[col + 1];
            float2 o0, o1;
            o0.x = (rsA * cs0) * (acc[mi][ni][0] - cz0 * rmA);
            o0.y = (rsA * cs1) * (acc[mi][ni][1] - cz1 * rmA);
            o1.x = (rsB * cs0) * (acc[mi][ni][2] - cz0 * rmB);
            o1.y = (rsB * cs1) * (acc[mi][ni][3] - cz1 * rmB);
            *(float2*)&C[(size_t)rA * N + col] = o0;
            *(float2*)&C[(size_t)rB * N + col] = o1;
        }
    }
}

// ---------------- RoPE apply ----------------
__global__ void k_rope_apply() {
    int t = blockIdx.x, hh = blockIdx.y, i = threadIdx.x;   // i 0..63
    float c = g_cos[t * 64 + i], s = g_sin[t * 64 + i];
    if (hh < NHQ) {
        const float* base = g_qkv + (size_t)t * QKVO + hh * HDIM;
        float x1 = base[i], x2 = base[64 + i];
        float* o = g_qr + (size_t)hh * TT * HDIM + (size_t)t * HDIM;
        o[i] = x1 * c - x2 * s;  o[64 + i] = x2 * c + x1 * s;
    } else {
        int kvh = hh - NHQ;
        const float* base = g_qkv + (size_t)t * QKVO + NHQ * HDIM + kvh * HDIM;
        float x1 = base[i], x2 = base[64 + i];
        float* o = g_kr + (size_t)kvh * TT * HDIM + (size_t)t * HDIM;
        o[i] = x1 * c - x2 * s;  o[64 + i] = x2 * c + x1 * s;
    }
}

// ======================================================================
// fp16 split-precision tensor-core flash attention (unchanged from R6).
// ======================================================================
#define FS 136
#define FLASH_SMEM2 ((128 * FS * 2 + 64 * FS * 4) * 2)

__device__ __forceinline__ void ldsm4t(uint32_t& r0, uint32_t& r1, uint32_t& r2, uint32_t& r3, uint32_t a) {
    asm volatile("ldmatrix.sync.aligned.m8n8.x4.trans.shared.b16 {%0,%1,%2,%3},[%4];\n"
                 : "=r"(r0), "=r"(r1), "=r"(r2), "=r"(r3) : "r"(a));
}
__device__ __forceinline__ void mmaf16(float* c, const uint32_t* a, uint32_t b0, uint32_t b1) {
    asm volatile("mma.sync.aligned.m16n8k16.row.col.f32.f16.f16.f32 "
                 "{%0,%1,%2,%3},{%4,%5,%6,%7},{%8,%9},{%0,%1,%2,%3};\n"
                 : "+f"(c[0]), "+f"(c[1]), "+f"(c[2]), "+f"(c[3])
                 : "r"(a[0]), "r"(a[1]), "r"(a[2]), "r"(a[3]), "r"(b0), "r"(b1));
}
__device__ __forceinline__ uint32_t ph2(__half a, __half b) {
    return (uint32_t)__half_as_ushort(a) | ((uint32_t)__half_as_ushort(b) << 16);
}
__device__ __forceinline__ void split4(float4 v, uint2& hi, uint2& lo) {
    __half a = __float2half_rn(v.x), b = __float2half_rn(v.y);
    __half c = __float2half_rn(v.z), d = __float2half_rn(v.w);
    hi.x = ph2(a, b); hi.y = ph2(c, d);
    lo.x = ph2(__float2half_rn(v.x - __half2float(a)), __float2half_rn(v.y - __half2float(b)));
    lo.y = ph2(__float2half_rn(v.z - __half2float(c)), __float2half_rn(v.w - __half2float(d)));
}
__device__ __forceinline__ void splitp(float x, float y, uint32_t& hi, uint32_t& lo) {
    __half a = __float2half_rn(x), b = __float2half_rn(y);
    hi = ph2(a, b);
    lo = ph2(__float2half_rn(x - __half2float(a)), __float2half_rn(y - __half2float(b)));
}

__global__ __launch_bounds__(256) void k_flash2() {
    extern __shared__ __half hsm[];
    __half* Qh = hsm;
    __half* Ql = Qh + 128 * FS;
    __half* Kh = Ql + 128 * FS;
    __half* Kl = Kh + 64 * FS;
    __half* Vh = Kl + 64 * FS;
    __half* Vl = Vh + 64 * FS;

    const int tid = threadIdx.x;
    const int w = tid >> 5, lane = tid & 31;
    const int g = lane >> 2, tq = lane & 3;
    const int head = blockIdx.y, kvh = head >> 2;
    const int qb = (int)(gridDim.x - 1 - blockIdx.x);
    const int q0 = qb * 128;

    const float* Qg = g_qr + (size_t)head * TT * HDIM + (size_t)q0 * HDIM;
    for (int idx = tid; idx < 128 * 32; idx += 256) {
        int r = idx >> 5, c = (idx & 31) << 2;
        float4 v = *(const float4*)&Qg[(size_t)r * HDIM + c];
        uint2 hi, lo; split4(v, hi, lo);
        *(uint2*)&Qh[r * FS + c] = hi;
        *(uint2*)&Ql[r * FS + c] = lo;
    }

    const int l7 = lane & 7, sel = lane >> 3;
    uint32_t aQh = s2u(Qh) + ((16 * w + (sel & 1) * 8 + l7) * FS + (sel >> 1) * 8) * 2;
    uint32_t aQl = aQh + 128 * FS * 2;
    uint32_t aKh = s2u(Kh) + (((sel >> 1) * 8 + l7) * FS + (sel & 1) * 8) * 2;
    uint32_t aKl = aKh + 64 * FS * 2;
    uint32_t aVh = s2u(Vh) + (((sel & 1) * 8 + l7) * FS + (sel >> 1) * 8) * 2;
    uint32_t aVl = aVh + 64 * FS * 2;

    float m0r = -INFINITY, m1r = -INFINITY, l0r = 0.f, l1r = 0.f;
    float O[16][4];
#pragma unroll
    for (int t = 0; t < 16; t++) { O[t][0]=0.f; O[t][1]=0.f; O[t][2]=0.f; O[t][3]=0.f; }

    const float* Kg = g_kr + (size_t)kvh * TT * HDIM;
    const float* Vg = g_qkv + (NHQ + NKVH) * HDIM + kvh * HDIM;
    const int rowg = q0 + 16 * w + g;
    const int nkb = 2 * qb + 2;

    for (int kb = 0; kb < nkb; kb++) {
        int k0 = kb * 64;
        __syncthreads();
        for (int idx = tid; idx < 64 * 32; idx += 256) {
            int r = idx >> 5, c = (idx & 31) << 2;
            uint2 hi, lo;
            float4 kv4 = *(const float4*)&Kg[(size_t)(k0 + r) * HDIM + c];
            split4(kv4, hi, lo);
            *(uint2*)&Kh[r * FS + c] = hi;  *(uint2*)&Kl[r * FS + c] = lo;
            float4 vv4 = *(const float4*)&Vg[(size_t)(k0 + r) * QKVO + c];
            split4(vv4, hi, lo);
            *(uint2*)&Vh[r * FS + c] = hi;  *(uint2*)&Vl[r * FS + c] = lo;
        }
        __syncthreads();

        float sc[8][4];
#pragma unroll
        for (int j = 0; j < 8; j++) { sc[j][0]=0.f; sc[j][1]=0.f; sc[j][2]=0.f; sc[j][3]=0.f; }
#pragma unroll
        for (int kt = 0; kt < 8; kt++) {
            uint32_t qa[4], ql_[4], kh[4], kl_[4];
            ldsm4(qa[0], qa[1], qa[2], qa[3], aQh + 32 * kt);
            ldsm4(ql_[0], ql_[1], ql_[2], ql_[3], aQl + 32 * kt);
#pragma unroll
            for (int p = 0; p < 4; p++) {
                ldsm4(kh[0], kh[1], kh[2], kh[3], aKh + 4352 * p + 32 * kt);
                ldsm4(kl_[0], kl_[1], kl_[2], kl_[3], aKl + 4352 * p + 32 * kt);
                mmaf16(sc[2 * p],     qa,  kh[0], kh[1]);
                mmaf16(sc[2 * p],     qa,  kl_[0], kl_[1]);
                mmaf16(sc[2 * p],     ql_, kh[0], kh[1]);
                mmaf16(sc[2 * p + 1], qa,  kh[2], kh[3]);
                mmaf16(sc[2 * p + 1], qa,  kl_[2], kl_[3]);
                mmaf16(sc[2 * p + 1], ql_, kh[2], kh[3]);
            }
        }

        bool tail = (kb >= 2 * qb);
#pragma unroll
        for (int j = 0; j < 8; j++) {
            int cb = k0 + 8 * j + 2 * tq;
#pragma unroll
            for (int e = 0; e < 2; e++) {
                float v0 = sc[j][e] * SCALE_QK;
                float v1 = sc[j][2 + e] * SCALE_QK;
                if (tail) {
                    if (cb + e > rowg)     v0 = -INFINITY;
                    if (cb + e > rowg + 8) v1 = -INFINITY;
                }
                sc[j][e] = v0; sc[j][2 + e] = v1;
            }
        }

        float mx0 = -INFINITY, mx1 = -INFINITY;
#pragma unroll
        for (int j = 0; j < 8; j++) {
            mx0 = fmaxf(mx0, fmaxf(sc[j][0], sc[j][1]));
            mx1 = fmaxf(mx1, fmaxf(sc[j][2], sc[j][3]));
        }
        mx0 = fmaxf(mx0, __shfl_xor_sync(0xffffffffu, mx0, 1));
        mx0 = fmaxf(mx0, __shfl_xor_sync(0xffffffffu, mx0, 2));
        mx1 = fmaxf(mx1, __shfl_xor_sync(0xffffffffu, mx1, 1));
        mx1 = fmaxf(mx1, __shfl_xor_sync(0xffffffffu, mx1, 2));
        float mn0 = fmaxf(m0r, mx0), mn1 = fmaxf(m1r, mx1);
        float c0 = __expf(m0r - mn0), c1 = __expf(m1r - mn1);
        m0r = mn0; m1r = mn1;
        float s0 = 0.f, s1 = 0.f;
#pragma unroll
        for (int j = 0; j < 8; j++) {
            sc[j][0] = __expf(sc[j][0] - mn0) * 1024.0f;
            sc[j][1] = __expf(sc[j][1] - mn0) * 1024.0f;
            sc[j][2] = __expf(sc[j][2] - mn1) * 1024.0f;
            sc[j][3] = __expf(sc[j][3] - mn1) * 1024.0f;
            s0 += sc[j][0] + sc[j][1];
            s1 += sc[j][2] + sc[j][3];
        }
        s0 += __shfl_xor_sync(0xffffffffu, s0, 1);
        s0 += __shfl_xor_sync(0xffffffffu, s0, 2);
        s1 += __shfl_xor_sync(0xffffffffu, s1, 1);
        s1 += __shfl_xor_sync(0xffffffffu, s1, 2);
        l0r = l0r * c0 + s0;
        l1r = l1r * c1 + s1;
#pragma unroll
        for (int t = 0; t < 16; t++) { O[t][0] *= c0; O[t][1] *= c0; O[t][2] *= c1; O[t][3] *= c1; }

#pragma unroll
        for (int jj = 0; jj < 4; jj++) {
            uint32_t pa[4], pl[4];
            splitp(sc[2 * jj][0],     sc[2 * jj][1],     pa[0], pl[0]);
            splitp(sc[2 * jj][2],     sc[2 * jj][3],     pa[1], pl[1]);
            splitp(sc[2 * jj + 1][0], sc[2 * jj + 1][1], pa[2], pl[2]);
            splitp(sc[2 * jj + 1][2], sc[2 * jj + 1][3], pa[3], pl[3]);
#pragma unroll
            for (int q = 0; q < 8; q++) {
                uint32_t vh[4], vl_[4];
                ldsm4t(vh[0], vh[1], vh[2], vh[3], aVh + 4352 * jj + 32 * q);
                ldsm4t(vl_[0], vl_[1], vl_[2], vl_[3], aVl + 4352 * jj + 32 * q);
                mmaf16(O[2 * q],     pa, vh[0], vh[1]);
                mmaf16(O[2 * q],     pa, vl_[0], vl_[1]);
                mmaf16(O[2 * q],     pl, vh[0], vh[1]);
                mmaf16(O[2 * q + 1], pa, vh[2], vh[3]);
                mmaf16(O[2 * q + 1], pa, vl_[2], vl_[3]);
                mmaf16(O[2 * q + 1], pl, vh[2], vh[3]);
            }
        }
    }

#pragma unroll
    for (int t = 0; t < 16; t++) {
        int col = head * HDIM + 8 * t + 2 * tq;
        float2 u;
        u.x = O[t][0] / l0r;  u.y = O[t][1] / l0r;
        *(float2*)&g_attn[(size_t)rowg * HIDN + col] = u;
        u.x = O[t][2] / l1r;  u.y = O[t][3] / l1r;
        *(float2*)&g_attn[(size_t)(rowg + 8) * HIDN + col] = u;
    }
}

// ---------------- dynamic quant with sum ----------------
__global__ __launch_bounds__(256) void k_quant() {
    __shared__ float xrow[HIDN];
    __shared__ float red[256];
    int t = blockIdx.x, tid = threadIdx.x;
    const float* src = g_attn + (size_t)t * HIDN;
    float amax = 0.f;
    for (int c = tid; c < HIDN; c += 256) { float x = src[c]; xrow[c] = x; amax = fmaxf(amax, fabsf(x)); }
    red[tid] = amax; __syncthreads();
    for (int k = 128; k > 0; k >>= 1) { if (tid < k) red[tid] = fmaxf(red[tid], red[tid + k]); __syncthreads(); }
    float s = fmaxf(red[0], 1e-8f) / 127.0f;
    __nv_bfloat16* q = g_q2 + (size_t)t * HIDN;
    float qs = 0.f;
    for (int c = tid; c < HIDN; c += 256) {
        float v = rintf(xrow[c] / s);
        v = fminf(fmaxf(v, -127.f), 127.f);
        q[c] = __float2bfloat16(v);
        qs += v;
    }
    __syncthreads();
    red[tid] = qs; __syncthreads();
    for (int k = 128; k > 0; k >>= 1) { if (tid < k) red[tid] += red[tid + k]; __syncthreads(); }
    if (tid == 0) { g_s2[t] = s; g_sum2[t] = red[0]; }
}

// ---------------- launch ----------------
extern "C" void kernel_launch(void* const* d_in, const int* in_sizes, int n_in,
                              void* d_out, int out_size) {
    const int*   positions   = (const int*)d_in[0];
    const int*   q_act       = (const int*)d_in[1];
    const float* act_scale   = (const float*)d_in[2];
    const int*   w_qkv_q     = (const int*)d_in[3];
    const float* w_qkv_scale = (const float*)d_in[4];
    const float* w_qkv_zero  = (const float*)d_in[5];
    const int*   w_o_q       = (const int*)d_in[6];
    const float* w_o_scale   = (const float*)d_in[7];
    const float* w_o_zero    = (const float*)d_in[8];
    float* out = (float*)d_out;

    __nv_bfloat16 *A, *Wqkv, *Wo, *q2;
    float *asum, *qkv, *s2, *sum2;
    cudaGetSymbolAddress((void**)&A,    g_A);
    cudaGetSymbolAddress((void**)&Wqkv, g_Wqkv);
    cudaGetSymbolAddress((void**)&Wo,   g_Wo);
    cudaGetSymbolAddress((void**)&q2,   g_q2);
    cudaGetSymbolAddress((void**)&asum, g_asum);
    cudaGetSymbolAddress((void**)&qkv,  g_qkv);
    cudaGetSymbolAddress((void**)&s2,   g_s2);
    cudaGetSymbolAddress((void**)&sum2, g_sum2);

    cudaFuncSetAttribute(k_flash2, cudaFuncAttributeMaxDynamicSharedMemorySize, FLASH_SMEM2);
    cudaFuncSetAttribute(k_gemm,   cudaFuncAttributeMaxDynamicSharedMemorySize, GEMM_SMEM);

    k_rope_tab<<<TT, 64>>>(positions);
    k_prep_a<<<TT, 256>>>(q_act);
    k_conv_w<<<2048, 256>>>(w_qkv_q, Wqkv, QKVO * HIDN);
    k_conv_w<<<2048, 256>>>(w_o_q, Wo, HIDN * HIDN);

    dim3 g1(QKVO / 128, TT / 256);
    k_gemm<<<g1, 256, GEMM_SMEM>>>(A, Wqkv, qkv, TT, QKVO, HIDN, act_scale, asum, w_qkv_scale, w_qkv_zero);

    dim3 g2(TT, NHQ + NKVH);
    k_rope_apply<<<g2, 64>>>();

    dim3 g3(TT / 128, NHQ);
    k_flash2<<<g3, 256, FLASH_SMEM2>>>();

    k_quant<<<TT, 256>>>();

    dim3 g4(HIDN / 128, TT / 256);
    k_gemm<<<g4, 256, GEMM_SMEM>>>(q2, Wo, out, TT, HIDN, HIDN, s2, sum2, w_o_scale, w_o_zero);
}